// round 16
// baseline (speedup 1.0000x reference)
#include <cuda_runtime.h>
#include <cuda_bf16.h>
#include <cuda_fp8.h>
#include <cstdint>
#include <math.h>

#define NN 2048
#define CC 1024
#define HH 8
#define DD 128
#define LIST_CAP 8192
#define XROW_CAP 4096
#define X_ELEMS ((size_t)NN * CC)      // 2M
#define W_ELEMS ((size_t)CC * CC)      // 1M

using bf16 = __nv_bfloat16;

// Scratch (device globals — no allocations anywhere)
__device__ bf16     g_Xh[X_ELEMS], g_Xl[X_ELEMS];  // X hi/lo bf16   8 MB
__device__ bf16     g_Wh[W_ELEMS], g_Wl[W_ELEMS];  // Wv hi/lo bf16  4 MB
__device__ bf16     g_vhat[(size_t)HH * NN * DD];  // v̂ bf16 (fixups) 4 MB
__device__ uint8_t  g_v8  [(size_t)HH * NN * DD];  // v̂ e4m3 (detect) 2 MB
__device__ float    g_Rsum[NN];
__device__ int      g_cnt;
__device__ uint2    g_list[LIST_CAP];
__device__ float    g_eval[LIST_CAP];
__device__ int      g_xcnt;
__device__ int      g_xrows[XROW_CAP];
__device__ uint32_t g_xbit[NN / 32];
__device__ uint32_t g_pbit[(size_t)NN * NN / 32];  // pair dedupe bitmap 512 KB

// ---------------------------------------------------------------------------
// helpers
// ---------------------------------------------------------------------------
__device__ __forceinline__ uint32_t sptr(const void* p) {
    return (uint32_t)__cvta_generic_to_shared(p);
}
#define CP_ASYNC16(dst, src) \
    asm volatile("cp.async.cg.shared.global [%0], [%1], 16;" \
                 :: "r"(dst), "l"(src))
#define CP_COMMIT() asm volatile("cp.async.commit_group;")
#define CP_WAIT(n)  asm volatile("cp.async.wait_group %0;" :: "n"(n))

__device__ __forceinline__ void ldmx4(uint32_t a, uint32_t* r) {
    asm volatile("ldmatrix.sync.aligned.m8n8.x4.shared.b16 {%0,%1,%2,%3}, [%4];"
                 : "=r"(r[0]), "=r"(r[1]), "=r"(r[2]), "=r"(r[3]) : "r"(a));
}
// NOT volatile — lets ptxas interleave HMMAs across accumulators.
__device__ __forceinline__ void mma_bf(float* c, const uint32_t* a,
                                       uint32_t b0, uint32_t b1) {
    asm("mma.sync.aligned.m16n8k16.row.col.f32.bf16.bf16.f32 "
        "{%0,%1,%2,%3}, {%4,%5,%6,%7}, {%8,%9}, {%0,%1,%2,%3};"
        : "+f"(c[0]), "+f"(c[1]), "+f"(c[2]), "+f"(c[3])
        : "r"(a[0]), "r"(a[1]), "r"(a[2]), "r"(a[3]), "r"(b0), "r"(b1));
}
__device__ __forceinline__ void mma_fp8(float* c, const uint32_t* a,
                                        uint32_t b0, uint32_t b1) {
    asm("mma.sync.aligned.m16n8k32.row.col.f32.e4m3.e4m3.f32 "
        "{%0,%1,%2,%3}, {%4,%5,%6,%7}, {%8,%9}, {%0,%1,%2,%3};"
        : "+f"(c[0]), "+f"(c[1]), "+f"(c[2]), "+f"(c[3])
        : "r"(a[0]), "r"(a[1]), "r"(a[2]), "r"(a[3]), "r"(b0), "r"(b1));
}
__device__ __forceinline__ uint32_t packbf(float x, float y) {
    __nv_bfloat162 h = __floats2bfloat162_rn(x, y);
    return *reinterpret_cast<uint32_t*>(&h);
}
__device__ __forceinline__ float2 unpackbf(uint32_t u) {
    __nv_bfloat162 h = *reinterpret_cast<__nv_bfloat162*>(&u);
    return __bfloat1622float2(h);
}
__device__ __forceinline__ void split2(float x, float y, uint32_t& hi, uint32_t& lo) {
    bf16 hx = __float2bfloat16_rn(x), hy = __float2bfloat16_rn(y);
    bf16 lx = __float2bfloat16_rn(x - __bfloat162float(hx));
    bf16 ly = __float2bfloat16_rn(y - __bfloat162float(hy));
    __nv_bfloat162 H = __halves2bfloat162(hx, hy);
    __nv_bfloat162 L = __halves2bfloat162(lx, ly);
    hi = *reinterpret_cast<uint32_t*>(&H);
    lo = *reinterpret_cast<uint32_t*>(&L);
}
__device__ __forceinline__ void mark_dirty(int r) {
    const uint32_t bit = 1u << (r & 31);
    uint32_t old = atomicOr(&g_xbit[r >> 5], bit);
    if (!(old & bit)) {
        int p = atomicAdd(&g_xcnt, 1);
        if (p < XROW_CAP) g_xrows[p] = r;
    }
}

// ---------------------------------------------------------------------------
// No-op kernels: pad the launch stream so ncu's profiled launch (#4) is qkv.
// ---------------------------------------------------------------------------
__global__ void kern_nop() {}

// ---------------------------------------------------------------------------
// Kernel 0: split X and Wv into hi/lo bf16 gmem arrays (one-time conversion).
// ---------------------------------------------------------------------------
__global__ __launch_bounds__(256)
void kern_split(const float* __restrict__ X, const float* __restrict__ Wv) {
    const size_t idx = ((size_t)blockIdx.x * 256 + threadIdx.x) * 4;
    const float* src; bf16 *dh, *dl; size_t off;
    if (idx < X_ELEMS) { src = X;  dh = g_Xh; dl = g_Xl; off = idx; }
    else               { src = Wv; dh = g_Wh; dl = g_Wl; off = idx - X_ELEMS; }
    const float4 v = *(const float4*)&src[off];
    uint32_t h0, l0, h1, l1;
    split2(v.x, v.y, h0, l0); split2(v.z, v.w, h1, l1);
    *(uint2*)&dh[off] = make_uint2(h0, h1);
    *(uint2*)&dl[off] = make_uint2(l0, l1);
}

// ---------------------------------------------------------------------------
// Kernel 1: v = X @ Wv^T (split-bf16, 3 MMA passes, pass-major). 32x128 tile
// per CTA -> grid (8,64)=512 CTAs, launch_bounds(256,3) -> 3 CTAs/SM (24
// warps) for mma.sync latency hiding (R15 showed occ=19.7% was the binder).
// n=128 = one full head so the fused L2-norm stays block-local. cp.async
// double-buffered. Writes BOTH output halves = v, g_vhat, g_v8, sim prefill;
// zero-inits scratch.
//
// smem per buffer (25600 B): Ah@0 (32x40 bf16), Al@2560, Bh@5120 (128x40),
// Bl@15360. x2 buffers + rsum[32].
// ---------------------------------------------------------------------------
__global__ __launch_bounds__(256, 3)
void kern_qkv(float* __restrict__ out) {
    extern __shared__ __align__(16) char qsm[];
    float* rsum = (float*)(qsm + 51200);
    const uint32_t smbase = sptr(qsm);

    const int m0 = blockIdx.y * 32, n0 = blockIdx.x * 128;
    const int tid = threadIdx.x, lane = tid & 31, wid = tid >> 5;
    const int wn = wid;                         // 8 warps, each 32(m) x 16(n)
    const int fr = lane & 15, fc = (lane >> 4) * 8;
    const int bid = blockIdx.y * 8 + blockIdx.x;   // 0..511

    // distributed zero-init of scratch
    g_pbit[(size_t)bid * 256 + tid] = 0;
    if (tid < 4) g_Rsum[bid * 4 + tid] = 0.0f;
    if (bid == 0) {
        if (tid < 64) g_xbit[tid] = 0;
        if (tid == 0) { g_cnt = 0; g_xcnt = 0; }
    }
    if (tid < 32) rsum[tid] = 0.0f;

    auto ISSUE = [&](int p, int k0) {
        const uint32_t base = smbase + p * 25600;
        // A: 32 rows x 32 cols, hi+lo: 256 cp16 total -> 1 per thread
        {
            const int mat = tid >> 7;                  // 0=hi, 1=lo
            const int rr = (tid & 127) >> 2, cq = tid & 3;
            const size_t gx = (size_t)(m0 + rr) * CC + k0 + cq * 8;
            const uint32_t s = base + mat * 2560 + rr * 80 + cq * 16;
            CP_ASYNC16(s, mat ? (const void*)&g_Xl[gx] : (const void*)&g_Xh[gx]);
        }
        // B: 128 rows x 32 cols, hi+lo: 4 cp16 per thread
        {
            const int rr = tid >> 1, ch = tid & 1;
            const size_t gw = (size_t)(n0 + rr) * CC + k0 + ch * 16;
            const uint32_t s = base + 5120 + rr * 80 + ch * 32;
            CP_ASYNC16(s,              &g_Wh[gw]);
            CP_ASYNC16(s + 16,         &g_Wh[gw + 8]);
            CP_ASYNC16(s + 10240,      &g_Wl[gw]);
            CP_ASYNC16(s + 10240 + 16, &g_Wl[gw + 8]);
        }
    };

    float acc[2][2][4] = {};   // i (m16 tile) x j (n8 tile) x frag

    ISSUE(0, 0); CP_COMMIT();
    int p = 0;
    for (int k0 = 0; k0 < CC; k0 += 32) {
        const bool has_next = (k0 + 32 < CC);
        if (has_next) { ISSUE(p ^ 1, k0 + 32); CP_COMMIT(); CP_WAIT(1); }
        else          { CP_WAIT(0); }
        __syncthreads();

        char* buf = qsm + p * 25600;
        bf16 (*Ah)[40] = (bf16(*)[40])buf;
        bf16 (*Al)[40] = (bf16(*)[40])(buf + 2560);
        bf16 (*Bh)[40] = (bf16(*)[40])(buf + 5120);
        bf16 (*Bl)[40] = (bf16(*)[40])(buf + 15360);
        #pragma unroll
        for (int ks = 0; ks < 32; ks += 16) {
            uint32_t ah[2][4], al[2][4], bh[4], bl[4];
            #pragma unroll
            for (int i = 0; i < 2; i++) {
                ldmx4(sptr(&Ah[i * 16 + fr][ks + fc]), ah[i]);
                ldmx4(sptr(&Al[i * 16 + fr][ks + fc]), al[i]);
            }
            ldmx4(sptr(&Bh[wn * 16 + fr][ks + fc]), bh);
            ldmx4(sptr(&Bl[wn * 16 + fr][ks + fc]), bl);
            // pass-major: hh, hl, lh
            #pragma unroll
            for (int i = 0; i < 2; i++) {
                mma_bf(acc[i][0], ah[i], bh[0], bh[2]);
                mma_bf(acc[i][1], ah[i], bh[1], bh[3]);
            }
            #pragma unroll
            for (int i = 0; i < 2; i++) {
                mma_bf(acc[i][0], ah[i], bl[0], bl[2]);
                mma_bf(acc[i][1], ah[i], bl[1], bl[3]);
            }
            #pragma unroll
            for (int i = 0; i < 2; i++) {
                mma_bf(acc[i][0], al[i], bh[0], bh[2]);
                mma_bf(acc[i][1], al[i], bh[1], bh[3]);
            }
        }
        __syncthreads();
        p ^= 1;
    }

    const int g = lane >> 2, t2 = (lane & 3) * 2;

    // per-row sumsq for this warp's n16 slice -> smem atomics
    #pragma unroll
    for (int i = 0; i < 2; i++)
        #pragma unroll
        for (int half = 0; half < 2; half++) {
            float s = 0.0f;
            #pragma unroll
            for (int j = 0; j < 2; j++) {
                float x = acc[i][j][half*2], y = acc[i][j][half*2+1];
                s = fmaf(x, x, s); s = fmaf(y, y, s);
            }
            s += __shfl_xor_sync(0xffffffffu, s, 1);
            s += __shfl_xor_sync(0xffffffffu, s, 2);
            if ((lane & 3) == 0)
                atomicAdd(&rsum[i * 16 + g + half * 8], s);
        }
    __syncthreads();

    const int h = n0 >> 7;
    #pragma unroll
    for (int i = 0; i < 2; i++)
        #pragma unroll
        for (int half = 0; half < 2; half++) {
            const int rowl = i * 16 + g + half * 8;
            const int row = m0 + rowl;
            const float inv = rsqrtf(rsum[rowl]);
            #pragma unroll
            for (int j = 0; j < 2; j++) {
                const int e = wn * 16 + j * 8 + t2;     // within-head channel
                const float x = acc[i][j][half*2], y = acc[i][j][half*2+1];
                const float2 v2 = make_float2(x, y);
                *(float2*)&out[(size_t)row * (2*CC) + CC + n0 + e] = v2;  // x_ori
                *(float2*)&out[(size_t)row * (2*CC) + n0 + e]      = v2;  // x ≈ v
                *(uint32_t*)&g_vhat[((size_t)h * NN + row) * DD + e] = packbf(x*inv, y*inv);
                __nv_fp8x2_storage_t p8 = __nv_cvt_float2_to_fp8x2(
                    make_float2(x*inv, y*inv), __NV_SATFINITE, __NV_E4M3);
                *(uint16_t*)&g_v8[((size_t)h * NN + row) * DD + e] = p8;
            }
        }

    // sim prefill: rows [bid*4, bid*4+4) ← zeros + 1.0 on the diagonal
    {
        float* sim = out + (size_t)NN * (2*CC);
        #pragma unroll
        for (int r = 0; r < 4; r++) {
            const int row = bid * 4 + r;
            float4 z0 = make_float4(0.f, 0.f, 0.f, 0.f);
            float4 z1 = make_float4(0.f, 0.f, 0.f, 0.f);
            const int d = row - tid * 8;
            if (d >= 0 && d < 4)      ((float*)&z0)[d] = 1.0f;
            else if (d >= 4 && d < 8) ((float*)&z1)[d - 4] = 1.0f;
            float* dst = sim + (size_t)row * NN + tid * 8;
            __stcs((float4*)dst, z0);
            __stcs((float4*)(dst + 4), z1);
        }
    }
}

// ---------------------------------------------------------------------------
// Kernel 2 (FP8 mma.sync): detection Gram with register-max pre-screen.
// ---------------------------------------------------------------------------
__global__ __launch_bounds__(256)
void kern_detect() {
    extern __shared__ __align__(16) char dsm[];   // 2 bufs x (As 18432 + Bs 18432)
    const uint32_t smbase = sptr(dsm);

    const int idx = blockIdx.x;
    int bj = (int)((sqrtf(8.0f * idx + 1.0f) - 1.0f) * 0.5f);
    while ((bj + 1) * (bj + 2) / 2 <= idx) bj++;
    while (bj * (bj + 1) / 2 > idx) bj--;
    const int bi = idx - bj * (bj + 1) / 2;         // 0 <= bi <= bj <= 15
    const int m0 = bi * 128, n0 = bj * 128;
    const bool offdiag = (bi != bj);

    const int tid = threadIdx.x, lane = tid & 31, wid = tid >> 5;
    const int wm = wid & 3, wn = wid >> 2;
    const int fr = lane & 15, fc = (lane >> 4) * 8;   // b16-unit column offset
    const int g = lane >> 2, t2 = (lane & 3) * 2;

    auto stage = [&](int bb, int h) {
        const uint8_t* __restrict__ V8 = g_v8 + (size_t)h * NN * DD;
        const int r = tid >> 1, a = tid & 1;
        const uint32_t base = smbase + bb * 36864 + r * 144 + a * 64;
        const uint8_t* srcA = &V8[(size_t)(m0 + r) * DD + a * 64];
        #pragma unroll
        for (int i = 0; i < 4; i++) CP_ASYNC16(base + i * 16, srcA + i * 16);
        if (offdiag) {
            const uint8_t* srcB = &V8[(size_t)(n0 + r) * DD + a * 64];
            #pragma unroll
            for (int i = 0; i < 4; i++) CP_ASYNC16(base + 18432 + i * 16, srcB + i * 16);
        }
    };

    stage(0, 0); CP_COMMIT();

    for (int h = 0; h < HH; h++) {
        const int bb = h & 1;
        CP_WAIT(0);
        __syncthreads();
        if (h < 7) { stage(bb ^ 1, h + 1); CP_COMMIT(); }

        uint16_t (*As)[72] = (uint16_t(*)[72])(dsm + bb * 36864);
        uint16_t (*Bs)[72] = (uint16_t(*)[72])(dsm + bb * 36864 + 18432);
        uint16_t (*Bsel)[72] = offdiag ? Bs : As;

        float acc[2][8][4] = {};
        #pragma unroll
        for (int ks = 0; ks < 4; ks++) {             // k32 chunks = 16 b16 units
            uint32_t a_[2][4], b_[4][4];
            #pragma unroll
            for (int i = 0; i < 2; i++)
                ldmx4(sptr(&As[wm * 32 + i * 16 + fr][ks * 16 + fc]), a_[i]);
            #pragma unroll
            for (int j = 0; j < 4; j++)
                ldmx4(sptr(&Bsel[wn * 64 + j * 16 + fr][ks * 16 + fc]), b_[j]);
            #pragma unroll
            for (int i = 0; i < 2; i++)
                #pragma unroll
                for (int j = 0; j < 4; j++) {
                    mma_fp8(acc[i][2*j],   a_[i], b_[j][0], b_[j][2]);
                    mma_fp8(acc[i][2*j+1], a_[i], b_[j][1], b_[j][3]);
                }
        }

        // register-max pre-screen: skip the scan unless something big exists
        float mx = -2.0f;
        #pragma unroll
        for (int i = 0; i < 2; i++)
            #pragma unroll
            for (int j = 0; j < 8; j++)
                #pragma unroll
                for (int t = 0; t < 4; t++)
                    mx = fmaxf(mx, acc[i][j][t]);

        if (mx > 0.5f) {
            #pragma unroll
            for (int i = 0; i < 2; i++)
                #pragma unroll
                for (int half = 0; half < 2; half++) {
                    const int grow = m0 + wm * 32 + i * 16 + g + half * 8;
                    #pragma unroll
                    for (int j = 0; j < 8; j++) {
                        #pragma unroll
                        for (int s = 0; s < 2; s++) {
                            const float v = acc[i][j][half*2 + s];
                            const int gcol = n0 + wn * 64 + j * 8 + t2 + s;
                            if (v > 0.5f && gcol != grow) {
                                mark_dirty(grow);
                                mark_dirty(gcol);
                                const int lo = min(grow, gcol), hi = max(grow, gcol);
                                const size_t pid = (size_t)lo * NN + hi;
                                const uint32_t bit = 1u << (pid & 31);
                                uint32_t old = atomicOr(&g_pbit[pid >> 5], bit);
                                if (!(old & bit)) {
                                    int pp = atomicAdd(&g_cnt, 2);
                                    if (pp + 1 < LIST_CAP) {
                                        g_list[pp]     = make_uint2((unsigned)lo, (unsigned)hi);
                                        g_list[pp + 1] = make_uint2((unsigned)hi, (unsigned)lo);
                                    }
                                }
                            }
                        }
                    }
                }
        }
        __syncthreads();
    }
}

// ---------------------------------------------------------------------------
// Fixup helpers: per-warp dot of v̂ rows for one head (all lanes get result)
// ---------------------------------------------------------------------------
__device__ __forceinline__ float warp_dot_head(int h, int n, int m, int lane) {
    const size_t bn = ((size_t)h * NN + n) * DD + lane * 4;
    const size_t bm = ((size_t)h * NN + m) * DD + lane * 4;
    uint2 a = *(const uint2*)&g_vhat[bn];
    uint2 b = *(const uint2*)&g_vhat[bm];
    float2 a0 = unpackbf(a.x), a1 = unpackbf(a.y);
    float2 b0 = unpackbf(b.x), b1 = unpackbf(b.y);
    float d = a0.x*b0.x + a0.y*b0.y + a1.x*b1.x + a1.y*b1.y;
    #pragma unroll
    for (int o = 16; o; o >>= 1) d += __shfl_xor_sync(0xffffffffu, d, o);
    return d;
}

// ---------------------------------------------------------------------------
// Kernel 3: exact x recompute for dirty rows (normally zero).
// ---------------------------------------------------------------------------
__global__ __launch_bounds__(256)
void kern_fixX(float* __restrict__ out) {
    const int lane = threadIdx.x & 31, h = threadIdx.x >> 5;
    const int cnt = min(g_xcnt, XROW_CAP);
    for (int i = blockIdx.x; i < cnt; i += gridDim.x) {
        const int n = g_xrows[i];
        float Z = 0.0f, xa[4] = {};
        for (int m = 0; m < NN; m++) {
            const float c = warp_dot_head(h, n, m, lane);
            const float e = __expf(25.0f * (c - 1.0f));
            Z += e;
            const float4 vm = *(const float4*)&out[(size_t)m * (2*CC) + CC + h * DD + lane * 4];
            xa[0] = fmaf(e, vm.x, xa[0]); xa[1] = fmaf(e, vm.y, xa[1]);
            xa[2] = fmaf(e, vm.z, xa[2]); xa[3] = fmaf(e, vm.w, xa[3]);
        }
        const float iz = 1.0f / Z;
        float4 o = make_float4(xa[0]*iz, xa[1]*iz, xa[2]*iz, xa[3]*iz);
        *(float4*)&out[(size_t)n * (2*CC) + h * DD + lane * 4] = o;
        __syncthreads();
    }
}

// ---------------------------------------------------------------------------
// Kernels 4/5: sim fixups for candidate pairs (normally zero).
// ---------------------------------------------------------------------------
__global__ __launch_bounds__(256)
void kern_fixSA() {
    __shared__ float sZ[8], sE[8], sAR[8];
    const int lane = threadIdx.x & 31, h = threadIdx.x >> 5;
    const int cnt = min(g_cnt, LIST_CAP);
    for (int i = blockIdx.x; i < cnt; i += gridDim.x) {
        const uint2 pr = g_list[i];
        const int n = (int)pr.x, m = (int)pr.y;
        float Z = 0.0f, et = 0.0f, dr = 0.0f;
        for (int mm = 0; mm < NN; mm++) {
            const float c = warp_dot_head(h, n, mm, lane);
            const float e = __expf(25.0f * (c - 1.0f));
            Z += e;
            if (mm == m) { et = e; dr = c; }
        }
        if (lane == 0) { sZ[h] = Z; sE[h] = et; sAR[h] = dr; }
        __syncthreads();
        if (threadIdx.x == 0) {
            float ar = 0.0f, sa = 0.0f;
            #pragma unroll
            for (int k = 0; k < 8; k++) { ar += sAR[k]; sa += sE[k] / sZ[k]; }
            if (ar > 6.0f) {
                const float ev = __expf(sa * 0.125f - 1.0f);
                g_eval[i] = ev;
                atomicAdd(&g_Rsum[n], ev);
            } else g_eval[i] = -1.0f;
        }
        __syncthreads();
    }
}

__global__ __launch_bounds__(256)
void kern_fixSB(float* __restrict__ out) {
    __shared__ float sZ[8], sE[8];
    const int lane = threadIdx.x & 31, h = threadIdx.x >> 5;
    const int cnt = min(g_cnt, LIST_CAP);
    float* sim = out + (size_t)NN * (2*CC);
    for (int i = blockIdx.x; i < cnt; i += gridDim.x) {
        const uint2 pr = g_list[i];
        const int n = (int)pr.x, m = (int)pr.y;
        const float ev = g_eval[i];
        if (ev >= 0.0f) {
            float Z = 0.0f, enn = 0.0f;
            for (int mm = 0; mm < NN; mm++) {
                const float c = warp_dot_head(h, n, mm, lane);
                const float e = __expf(25.0f * (c - 1.0f));
                Z += e;
                if (mm == n) enn = e;
            }
            if (lane == 0) { sZ[h] = Z; sE[h] = enn; }
            __syncthreads();
            if (threadIdx.x == 0) {
                float sa = 0.0f;
                #pragma unroll
                for (int k = 0; k < 8; k++) sa += sE[k] / sZ[k];
                const float en2 = __expf(sa * 0.125f - 1.0f);   // e(n,n)
                const float R = en2 + g_Rsum[n];
                sim[(size_t)n * NN + m] = ev / R;
                sim[(size_t)n * NN + n] = en2 / R;
            }
            __syncthreads();
        }
    }
}

// ---------------------------------------------------------------------------
extern "C" void kernel_launch(void* const* d_in, const int* in_sizes, int n_in,
                              void* d_out, int out_size) {
    const float* x_cls = (const float*)d_in[0];
    const float* W_cls = (const float*)d_in[4];
    float* out = (float*)d_out;
    const float* Wv = W_cls + (size_t)2 * CC * CC;

    const int qkv_smem = 2 * 25600 + 32 * 4;          // 51328 B (3 CTAs/SM)
    const int det_smem = 2 * 36864;                   // 73728 B
    static bool attr_done = false;
    if (!attr_done) {
        cudaFuncSetAttribute(kern_qkv, cudaFuncAttributeMaxDynamicSharedMemorySize,
                             qkv_smem);
        cudaFuncSetAttribute(kern_detect, cudaFuncAttributeMaxDynamicSharedMemorySize,
                             det_smem);
        attr_done = true;
    }

    kern_nop   <<<1, 32>>>();
    kern_nop   <<<1, 32>>>();
    kern_split <<<3072, 256>>>(x_cls, Wv);
    kern_qkv   <<<dim3(8, 64), 256, qkv_smem>>>(out);
    kern_detect<<<136, 256, det_smem>>>();
    kern_fixX  <<<32, 256>>>(out);
    kern_fixSA <<<16, 256>>>();
    kern_fixSB <<<16, 256>>>(out);
}

// round 17
// speedup vs baseline: 1.4998x; 1.4998x over previous
#include <cuda_runtime.h>
#include <cuda_bf16.h>
#include <cuda_fp8.h>
#include <cstdint>
#include <math.h>

#define NN 2048
#define CC 1024
#define HH 8
#define DD 128
#define LIST_CAP 8192
#define XROW_CAP 4096
#define X_ELEMS ((size_t)NN * CC)      // 2M
#define W_ELEMS ((size_t)CC * CC)      // 1M

using bf16 = __nv_bfloat16;

// Scratch (device globals — no allocations anywhere)
__device__ bf16     g_Xh[X_ELEMS], g_Xl[X_ELEMS];  // X hi/lo bf16   8 MB
__device__ bf16     g_Wh[W_ELEMS], g_Wl[W_ELEMS];  // Wv hi/lo bf16  4 MB
__device__ bf16     g_vhat[(size_t)HH * NN * DD];  // v̂ bf16 (fixups) 4 MB
__device__ uint8_t  g_v8  [(size_t)HH * NN * DD];  // v̂ e4m3 (detect) 2 MB
__device__ float    g_Rsum[NN];
__device__ int      g_cnt;
__device__ uint2    g_list[LIST_CAP];
__device__ float    g_eval[LIST_CAP];
__device__ int      g_xcnt;
__device__ int      g_xrows[XROW_CAP];
__device__ uint32_t g_xbit[NN / 32];
__device__ uint32_t g_pbit[(size_t)NN * NN / 32];  // pair dedupe bitmap 512 KB

// ---------------------------------------------------------------------------
// helpers
// ---------------------------------------------------------------------------
__device__ __forceinline__ uint32_t sptr(const void* p) {
    return (uint32_t)__cvta_generic_to_shared(p);
}
#define CP_ASYNC16(dst, src) \
    asm volatile("cp.async.cg.shared.global [%0], [%1], 16;" \
                 :: "r"(dst), "l"(src))
#define CP_COMMIT() asm volatile("cp.async.commit_group;")
#define CP_WAIT(n)  asm volatile("cp.async.wait_group %0;" :: "n"(n))

__device__ __forceinline__ void ldmx4(uint32_t a, uint32_t* r) {
    asm volatile("ldmatrix.sync.aligned.m8n8.x4.shared.b16 {%0,%1,%2,%3}, [%4];"
                 : "=r"(r[0]), "=r"(r[1]), "=r"(r[2]), "=r"(r[3]) : "r"(a));
}
// NOT volatile — lets ptxas interleave HMMAs across accumulators.
__device__ __forceinline__ void mma_bf(float* c, const uint32_t* a,
                                       uint32_t b0, uint32_t b1) {
    asm("mma.sync.aligned.m16n8k16.row.col.f32.bf16.bf16.f32 "
        "{%0,%1,%2,%3}, {%4,%5,%6,%7}, {%8,%9}, {%0,%1,%2,%3};"
        : "+f"(c[0]), "+f"(c[1]), "+f"(c[2]), "+f"(c[3])
        : "r"(a[0]), "r"(a[1]), "r"(a[2]), "r"(a[3]), "r"(b0), "r"(b1));
}
__device__ __forceinline__ void mma_fp8(float* c, const uint32_t* a,
                                        uint32_t b0, uint32_t b1) {
    asm("mma.sync.aligned.m16n8k32.row.col.f32.e4m3.e4m3.f32 "
        "{%0,%1,%2,%3}, {%4,%5,%6,%7}, {%8,%9}, {%0,%1,%2,%3};"
        : "+f"(c[0]), "+f"(c[1]), "+f"(c[2]), "+f"(c[3])
        : "r"(a[0]), "r"(a[1]), "r"(a[2]), "r"(a[3]), "r"(b0), "r"(b1));
}
__device__ __forceinline__ uint32_t packbf(float x, float y) {
    __nv_bfloat162 h = __floats2bfloat162_rn(x, y);
    return *reinterpret_cast<uint32_t*>(&h);
}
__device__ __forceinline__ float2 unpackbf(uint32_t u) {
    __nv_bfloat162 h = *reinterpret_cast<__nv_bfloat162*>(&u);
    return __bfloat1622float2(h);
}
__device__ __forceinline__ void split2(float x, float y, uint32_t& hi, uint32_t& lo) {
    bf16 hx = __float2bfloat16_rn(x), hy = __float2bfloat16_rn(y);
    bf16 lx = __float2bfloat16_rn(x - __bfloat162float(hx));
    bf16 ly = __float2bfloat16_rn(y - __bfloat162float(hy));
    __nv_bfloat162 H = __halves2bfloat162(hx, hy);
    __nv_bfloat162 L = __halves2bfloat162(lx, ly);
    hi = *reinterpret_cast<uint32_t*>(&H);
    lo = *reinterpret_cast<uint32_t*>(&L);
}
__device__ __forceinline__ void mark_dirty(int r) {
    const uint32_t bit = 1u << (r & 31);
    uint32_t old = atomicOr(&g_xbit[r >> 5], bit);
    if (!(old & bit)) {
        int p = atomicAdd(&g_xcnt, 1);
        if (p < XROW_CAP) g_xrows[p] = r;
    }
}

// ---------------------------------------------------------------------------
// No-op kernel: pads the launch stream so ncu's profiled launch (#4) = detect.
// ---------------------------------------------------------------------------
__global__ void kern_nop() {}

// ---------------------------------------------------------------------------
// Kernel 0: split X and Wv into hi/lo bf16 gmem arrays (one-time conversion).
// ---------------------------------------------------------------------------
__global__ __launch_bounds__(256)
void kern_split(const float* __restrict__ X, const float* __restrict__ Wv) {
    const size_t idx = ((size_t)blockIdx.x * 256 + threadIdx.x) * 4;
    const float* src; bf16 *dh, *dl; size_t off;
    if (idx < X_ELEMS) { src = X;  dh = g_Xh; dl = g_Xl; off = idx; }
    else               { src = Wv; dh = g_Wh; dl = g_Wl; off = idx - X_ELEMS; }
    const float4 v = *(const float4*)&src[off];
    uint32_t h0, l0, h1, l1;
    split2(v.x, v.y, h0, l0); split2(v.z, v.w, h1, l1);
    *(uint2*)&dh[off] = make_uint2(h0, h1);
    *(uint2*)&dl[off] = make_uint2(l0, l1);
}

// ---------------------------------------------------------------------------
// Kernel 1 (R15 config — best measured): v = X @ Wv^T (split-bf16, 3 passes,
// pass-major). 64x128 tile/block, grid (8,32)=256 -> 2 CTAs/SM. cp.async
// double-buffered; fused L2 normalize. Writes BOTH output halves = v, g_vhat,
// g_v8, sim prefill; zero-inits scratch.
// ---------------------------------------------------------------------------
__global__ __launch_bounds__(256, 2)
void kern_qkv(float* __restrict__ out) {
    extern __shared__ __align__(16) char qsm[];
    float* rsum = (float*)(qsm + 61440);
    const uint32_t smbase = sptr(qsm);

    const int m0 = blockIdx.y * 64, n0 = blockIdx.x * 128;
    const int tid = threadIdx.x, lane = tid & 31, wid = tid >> 5;
    const int wm = wid & 1, wn = wid >> 1;      // 2 m-groups x 4 n-groups (32x32)
    const int fr = lane & 15, fc = (lane >> 4) * 8;
    const int bid = blockIdx.y * 8 + blockIdx.x;   // 0..255

    // distributed zero-init of scratch
    #pragma unroll
    for (int i = 0; i < 2; i++) g_pbit[(size_t)bid * 512 + i * 256 + tid] = 0;
    if (tid < 8) g_Rsum[bid * 8 + tid] = 0.0f;
    if (bid == 0) {
        if (tid < 64) g_xbit[tid] = 0;
        if (tid == 0) { g_cnt = 0; g_xcnt = 0; }
    }
    if (tid < 64) rsum[tid] = 0.0f;

    auto ISSUE = [&](int p, int k0) {
        const uint32_t base = smbase + p * 30720;
        {
            const int r = tid >> 2, cq = tid & 3;
            const size_t gx = (size_t)(m0 + r) * CC + k0 + cq * 8;
            const uint32_t s = base + r * 80 + cq * 16;
            CP_ASYNC16(s,        &g_Xh[gx]);
            CP_ASYNC16(s + 5120, &g_Xl[gx]);
        }
        {
            const int r = tid >> 1, ch = tid & 1;
            const size_t gw = (size_t)(n0 + r) * CC + k0 + ch * 16;
            const uint32_t s = base + 10240 + r * 80 + ch * 32;
            CP_ASYNC16(s,             &g_Wh[gw]);
            CP_ASYNC16(s + 16,        &g_Wh[gw + 8]);
            CP_ASYNC16(s + 10240,     &g_Wl[gw]);
            CP_ASYNC16(s + 10240 + 16,&g_Wl[gw + 8]);
        }
    };

    float acc[2][4][4] = {};

    ISSUE(0, 0); CP_COMMIT();
    int p = 0;
    for (int k0 = 0; k0 < CC; k0 += 32) {
        const bool has_next = (k0 + 32 < CC);
        if (has_next) { ISSUE(p ^ 1, k0 + 32); CP_COMMIT(); CP_WAIT(1); }
        else          { CP_WAIT(0); }
        __syncthreads();

        char* buf = qsm + p * 30720;
        bf16 (*Ah)[40] = (bf16(*)[40])buf;
        bf16 (*Al)[40] = (bf16(*)[40])(buf + 5120);
        bf16 (*Bh)[40] = (bf16(*)[40])(buf + 10240);
        bf16 (*Bl)[40] = (bf16(*)[40])(buf + 20480);
        #pragma unroll
        for (int ks = 0; ks < 32; ks += 16) {
            uint32_t ah[2][4], al[2][4], bh[2][4], bl[2][4];
            #pragma unroll
            for (int i = 0; i < 2; i++) {
                ldmx4(sptr(&Ah[wm * 32 + i * 16 + fr][ks + fc]), ah[i]);
                ldmx4(sptr(&Al[wm * 32 + i * 16 + fr][ks + fc]), al[i]);
            }
            #pragma unroll
            for (int j = 0; j < 2; j++) {
                ldmx4(sptr(&Bh[wn * 32 + j * 16 + fr][ks + fc]), bh[j]);
                ldmx4(sptr(&Bl[wn * 32 + j * 16 + fr][ks + fc]), bl[j]);
            }
            // pass-major order: same accumulator reused at distance 8
            #pragma unroll
            for (int i = 0; i < 2; i++)
                #pragma unroll
                for (int j = 0; j < 2; j++) {
                    mma_bf(acc[i][2*j],   ah[i], bh[j][0], bh[j][2]);
                    mma_bf(acc[i][2*j+1], ah[i], bh[j][1], bh[j][3]);
                }
            #pragma unroll
            for (int i = 0; i < 2; i++)
                #pragma unroll
                for (int j = 0; j < 2; j++) {
                    mma_bf(acc[i][2*j],   ah[i], bl[j][0], bl[j][2]);
                    mma_bf(acc[i][2*j+1], ah[i], bl[j][1], bl[j][3]);
                }
            #pragma unroll
            for (int i = 0; i < 2; i++)
                #pragma unroll
                for (int j = 0; j < 2; j++) {
                    mma_bf(acc[i][2*j],   al[i], bh[j][0], bh[j][2]);
                    mma_bf(acc[i][2*j+1], al[i], bh[j][1], bh[j][3]);
                }
        }
        __syncthreads();
        p ^= 1;
    }

    const int g = lane >> 2, t2 = (lane & 3) * 2;

    #pragma unroll
    for (int i = 0; i < 2; i++)
        #pragma unroll
        for (int half = 0; half < 2; half++) {
            float s = 0.0f;
            #pragma unroll
            for (int j = 0; j < 4; j++) {
                float x = acc[i][j][half*2], y = acc[i][j][half*2+1];
                s = fmaf(x, x, s); s = fmaf(y, y, s);
            }
            s += __shfl_xor_sync(0xffffffffu, s, 1);
            s += __shfl_xor_sync(0xffffffffu, s, 2);
            if ((lane & 3) == 0)
                atomicAdd(&rsum[wm * 32 + i * 16 + g + half * 8], s);
        }
    __syncthreads();

    const int h = n0 >> 7;
    #pragma unroll
    for (int i = 0; i < 2; i++)
        #pragma unroll
        for (int half = 0; half < 2; half++) {
            const int rowl = wm * 32 + i * 16 + g + half * 8;
            const int row = m0 + rowl;
            const float inv = rsqrtf(rsum[rowl]);
            #pragma unroll
            for (int j = 0; j < 4; j++) {
                const int e = wn * 32 + j * 8 + t2;     // within-head channel
                const float x = acc[i][j][half*2], y = acc[i][j][half*2+1];
                const float2 v2 = make_float2(x, y);
                *(float2*)&out[(size_t)row * (2*CC) + CC + n0 + e] = v2;  // x_ori
                *(float2*)&out[(size_t)row * (2*CC) + n0 + e]      = v2;  // x ≈ v
                *(uint32_t*)&g_vhat[((size_t)h * NN + row) * DD + e] = packbf(x*inv, y*inv);
                __nv_fp8x2_storage_t p8 = __nv_cvt_float2_to_fp8x2(
                    make_float2(x*inv, y*inv), __NV_SATFINITE, __NV_E4M3);
                *(uint16_t*)&g_v8[((size_t)h * NN + row) * DD + e] = p8;
            }
        }

    // sim prefill: rows [bid*8, bid*8+8) ← zeros + 1.0 on the diagonal
    {
        float* sim = out + (size_t)NN * (2*CC);
        #pragma unroll
        for (int r = 0; r < 8; r++) {
            const int row = bid * 8 + r;
            float4 z0 = make_float4(0.f, 0.f, 0.f, 0.f);
            float4 z1 = make_float4(0.f, 0.f, 0.f, 0.f);
            const int d = row - tid * 8;
            if (d >= 0 && d < 4)      ((float*)&z0)[d] = 1.0f;
            else if (d >= 4 && d < 8) ((float*)&z1)[d - 4] = 1.0f;
            float* dst = sim + (size_t)row * NN + tid * 8;
            __stcs((float4*)dst, z0);
            __stcs((float4*)(dst + 4), z1);
        }
    }
}

// ---------------------------------------------------------------------------
// Kernel 2 (FP8 mma.sync): detection Gram, HEAD-PARALLEL grid (136, 8) =
// 1088 CTAs. Each CTA: one head, one triangular tile; single-buffered
// cp.async stage, one 64-MMA fp8 burst, register-max pre-screen. Cross-CTA
// residency (2+/SM, 3.7 waves) hides stage latency that the old serial
// 8-head loop exposed. Screening atomics are idempotent across heads.
// ---------------------------------------------------------------------------
__global__ __launch_bounds__(256, 2)
void kern_detect() {
    extern __shared__ __align__(16) char dsm[];   // As 18432 + Bs 18432
    const uint32_t smbase = sptr(dsm);

    const int idx = blockIdx.x;
    const int h = blockIdx.y;
    int bj = (int)((sqrtf(8.0f * idx + 1.0f) - 1.0f) * 0.5f);
    while ((bj + 1) * (bj + 2) / 2 <= idx) bj++;
    while (bj * (bj + 1) / 2 > idx) bj--;
    const int bi = idx - bj * (bj + 1) / 2;         // 0 <= bi <= bj <= 15
    const int m0 = bi * 128, n0 = bj * 128;
    const bool offdiag = (bi != bj);

    const int tid = threadIdx.x, lane = tid & 31, wid = tid >> 5;
    const int wm = wid & 3, wn = wid >> 2;
    const int fr = lane & 15, fc = (lane >> 4) * 8;   // b16-unit column offset
    const int g = lane >> 2, t2 = (lane & 3) * 2;

    // stage this head's tiles
    {
        const uint8_t* __restrict__ V8 = g_v8 + (size_t)h * NN * DD;
        const int r = tid >> 1, a = tid & 1;
        const uint32_t base = smbase + r * 144 + a * 64;
        const uint8_t* srcA = &V8[(size_t)(m0 + r) * DD + a * 64];
        #pragma unroll
        for (int i = 0; i < 4; i++) CP_ASYNC16(base + i * 16, srcA + i * 16);
        if (offdiag) {
            const uint8_t* srcB = &V8[(size_t)(n0 + r) * DD + a * 64];
            #pragma unroll
            for (int i = 0; i < 4; i++) CP_ASYNC16(base + 18432 + i * 16, srcB + i * 16);
        }
    }
    CP_COMMIT(); CP_WAIT(0);
    __syncthreads();

    uint16_t (*As)[72] = (uint16_t(*)[72])dsm;
    uint16_t (*Bs)[72] = (uint16_t(*)[72])(dsm + 18432);
    uint16_t (*Bsel)[72] = offdiag ? Bs : As;

    float acc[2][8][4] = {};
    #pragma unroll
    for (int ks = 0; ks < 4; ks++) {             // k32 chunks = 16 b16 units
        uint32_t a_[2][4], b_[4][4];
        #pragma unroll
        for (int i = 0; i < 2; i++)
            ldmx4(sptr(&As[wm * 32 + i * 16 + fr][ks * 16 + fc]), a_[i]);
        #pragma unroll
        for (int j = 0; j < 4; j++)
            ldmx4(sptr(&Bsel[wn * 64 + j * 16 + fr][ks * 16 + fc]), b_[j]);
        #pragma unroll
        for (int i = 0; i < 2; i++)
            #pragma unroll
            for (int j = 0; j < 4; j++) {
                mma_fp8(acc[i][2*j],   a_[i], b_[j][0], b_[j][2]);
                mma_fp8(acc[i][2*j+1], a_[i], b_[j][1], b_[j][3]);
            }
    }

    // register-max pre-screen: skip the scan unless something big exists
    float mx = -2.0f;
    #pragma unroll
    for (int i = 0; i < 2; i++)
        #pragma unroll
        for (int j = 0; j < 8; j++)
            #pragma unroll
            for (int t = 0; t < 4; t++)
                mx = fmaxf(mx, acc[i][j][t]);

    if (mx > 0.5f) {
        #pragma unroll
        for (int i = 0; i < 2; i++)
            #pragma unroll
            for (int half = 0; half < 2; half++) {
                const int grow = m0 + wm * 32 + i * 16 + g + half * 8;
                #pragma unroll
                for (int j = 0; j < 8; j++) {
                    #pragma unroll
                    for (int s = 0; s < 2; s++) {
                        const float v = acc[i][j][half*2 + s];
                        const int gcol = n0 + wn * 64 + j * 8 + t2 + s;
                        if (v > 0.5f && gcol != grow) {
                            mark_dirty(grow);
                            mark_dirty(gcol);
                            const int lo = min(grow, gcol), hi = max(grow, gcol);
                            const size_t pid = (size_t)lo * NN + hi;
                            const uint32_t bit = 1u << (pid & 31);
                            uint32_t old = atomicOr(&g_pbit[pid >> 5], bit);
                            if (!(old & bit)) {
                                int pp = atomicAdd(&g_cnt, 2);
                                if (pp + 1 < LIST_CAP) {
                                    g_list[pp]     = make_uint2((unsigned)lo, (unsigned)hi);
                                    g_list[pp + 1] = make_uint2((unsigned)hi, (unsigned)lo);
                                }
                            }
                        }
                    }
                }
            }
    }
}

// ---------------------------------------------------------------------------
// Fixup helpers: per-warp dot of v̂ rows for one head (all lanes get result)
// ---------------------------------------------------------------------------
__device__ __forceinline__ float warp_dot_head(int h, int n, int m, int lane) {
    const size_t bn = ((size_t)h * NN + n) * DD + lane * 4;
    const size_t bm = ((size_t)h * NN + m) * DD + lane * 4;
    uint2 a = *(const uint2*)&g_vhat[bn];
    uint2 b = *(const uint2*)&g_vhat[bm];
    float2 a0 = unpackbf(a.x), a1 = unpackbf(a.y);
    float2 b0 = unpackbf(b.x), b1 = unpackbf(b.y);
    float d = a0.x*b0.x + a0.y*b0.y + a1.x*b1.x + a1.y*b1.y;
    #pragma unroll
    for (int o = 16; o; o >>= 1) d += __shfl_xor_sync(0xffffffffu, d, o);
    return d;
}

// ---------------------------------------------------------------------------
// Kernel 3: exact x recompute for dirty rows (normally zero).
// ---------------------------------------------------------------------------
__global__ __launch_bounds__(256)
void kern_fixX(float* __restrict__ out) {
    const int lane = threadIdx.x & 31, h = threadIdx.x >> 5;
    const int cnt = min(g_xcnt, XROW_CAP);
    for (int i = blockIdx.x; i < cnt; i += gridDim.x) {
        const int n = g_xrows[i];
        float Z = 0.0f, xa[4] = {};
        for (int m = 0; m < NN; m++) {
            const float c = warp_dot_head(h, n, m, lane);
            const float e = __expf(25.0f * (c - 1.0f));
            Z += e;
            const float4 vm = *(const float4*)&out[(size_t)m * (2*CC) + CC + h * DD + lane * 4];
            xa[0] = fmaf(e, vm.x, xa[0]); xa[1] = fmaf(e, vm.y, xa[1]);
            xa[2] = fmaf(e, vm.z, xa[2]); xa[3] = fmaf(e, vm.w, xa[3]);
        }
        const float iz = 1.0f / Z;
        float4 o = make_float4(xa[0]*iz, xa[1]*iz, xa[2]*iz, xa[3]*iz);
        *(float4*)&out[(size_t)n * (2*CC) + h * DD + lane * 4] = o;
        __syncthreads();
    }
}

// ---------------------------------------------------------------------------
// Kernels 4/5: sim fixups for candidate pairs (normally zero).
// ---------------------------------------------------------------------------
__global__ __launch_bounds__(256)
void kern_fixSA() {
    __shared__ float sZ[8], sE[8], sAR[8];
    const int lane = threadIdx.x & 31, h = threadIdx.x >> 5;
    const int cnt = min(g_cnt, LIST_CAP);
    for (int i = blockIdx.x; i < cnt; i += gridDim.x) {
        const uint2 pr = g_list[i];
        const int n = (int)pr.x, m = (int)pr.y;
        float Z = 0.0f, et = 0.0f, dr = 0.0f;
        for (int mm = 0; mm < NN; mm++) {
            const float c = warp_dot_head(h, n, mm, lane);
            const float e = __expf(25.0f * (c - 1.0f));
            Z += e;
            if (mm == m) { et = e; dr = c; }
        }
        if (lane == 0) { sZ[h] = Z; sE[h] = et; sAR[h] = dr; }
        __syncthreads();
        if (threadIdx.x == 0) {
            float ar = 0.0f, sa = 0.0f;
            #pragma unroll
            for (int k = 0; k < 8; k++) { ar += sAR[k]; sa += sE[k] / sZ[k]; }
            if (ar > 6.0f) {
                const float ev = __expf(sa * 0.125f - 1.0f);
                g_eval[i] = ev;
                atomicAdd(&g_Rsum[n], ev);
            } else g_eval[i] = -1.0f;
        }
        __syncthreads();
    }
}

__global__ __launch_bounds__(256)
void kern_fixSB(float* __restrict__ out) {
    __shared__ float sZ[8], sE[8];
    const int lane = threadIdx.x & 31, h = threadIdx.x >> 5;
    const int cnt = min(g_cnt, LIST_CAP);
    float* sim = out + (size_t)NN * (2*CC);
    for (int i = blockIdx.x; i < cnt; i += gridDim.x) {
        const uint2 pr = g_list[i];
        const int n = (int)pr.x, m = (int)pr.y;
        const float ev = g_eval[i];
        if (ev >= 0.0f) {
            float Z = 0.0f, enn = 0.0f;
            for (int mm = 0; mm < NN; mm++) {
                const float c = warp_dot_head(h, n, mm, lane);
                const float e = __expf(25.0f * (c - 1.0f));
                Z += e;
                if (mm == n) enn = e;
            }
            if (lane == 0) { sZ[h] = Z; sE[h] = enn; }
            __syncthreads();
            if (threadIdx.x == 0) {
                float sa = 0.0f;
                #pragma unroll
                for (int k = 0; k < 8; k++) sa += sE[k] / sZ[k];
                const float en2 = __expf(sa * 0.125f - 1.0f);   // e(n,n)
                const float R = en2 + g_Rsum[n];
                sim[(size_t)n * NN + m] = ev / R;
                sim[(size_t)n * NN + n] = en2 / R;
            }
            __syncthreads();
        }
    }
}

// ---------------------------------------------------------------------------
extern "C" void kernel_launch(void* const* d_in, const int* in_sizes, int n_in,
                              void* d_out, int out_size) {
    const float* x_cls = (const float*)d_in[0];
    const float* W_cls = (const float*)d_in[4];
    float* out = (float*)d_out;
    const float* Wv = W_cls + (size_t)2 * CC * CC;

    const int qkv_smem = 2 * 30720 + 64 * 4;          // 61696 B (2 CTAs/SM)
    const int det_smem = 36864;                       // single buffer
    static bool attr_done = false;
    if (!attr_done) {
        cudaFuncSetAttribute(kern_qkv, cudaFuncAttributeMaxDynamicSharedMemorySize,
                             qkv_smem);
        cudaFuncSetAttribute(kern_detect, cudaFuncAttributeMaxDynamicSharedMemorySize,
                             det_smem);
        attr_done = true;
    }

    // stream: nop, split, qkv, detect, ... -> ncu's profiled launch #4 = detect
    kern_nop   <<<1, 32>>>();
    kern_split <<<3072, 256>>>(x_cls, Wv);
    kern_qkv   <<<dim3(8, 32), 256, qkv_smem>>>(out);
    kern_detect<<<dim3(136, 8), 256, det_smem>>>();
    kern_fixX  <<<32, 256>>>(out);
    kern_fixSA <<<16, 256>>>();
    kern_fixSB <<<16, 256>>>(out);
}